// round 12
// baseline (speedup 1.0000x reference)
#include <cuda_runtime.h>
#include <cuda_fp16.h>
#include <math.h>
#include <stdint.h>

#define N_  4096
#define H_  64
#define T_  6
#define G_  16
#define TH_ 192    // 3*H
#define TD_ 384    // T*H

// ---------------- device scratch ----------------
__device__ float g_A[H_ * TH_];            // A[m][r] = Wc[r][m]
__device__ __align__(16) __half g_qr16[N_ * TD_];       // q fp16 [n][t*64+d]
__device__ __align__(16) __half g_k16 [N_ * TD_];       // k fp16 [n][t*64+d]
__device__ __align__(16) __half g_v16 [N_ * H_];        // v fp16 [n][e]
__device__ __align__(16) float  g_updf[N_ * H_];        // update fp32 [n][e] (atomic)
__device__ __half g_B16[H_ * H_ * H_];     // W_tp fp16, [i][j][k]
__device__ int   g_seg[G_ + 1];

#define RSTRIDE 144   // 72 fp16 row stride (bytes)

// ---------------- PTX helpers ----------------
__device__ __forceinline__ uint32_t smem_u32(const void* p) {
    uint32_t a;
    asm("{ .reg .u64 t; cvta.to.shared.u64 t, %1; cvt.u32.u64 %0, t; }" : "=r"(a) : "l"(p));
    return a;
}
#define LDSM_X4(r, addr) \
    asm volatile("ldmatrix.sync.aligned.m8n8.x4.shared.b16 {%0,%1,%2,%3}, [%4];" \
        : "=r"((r)[0]), "=r"((r)[1]), "=r"((r)[2]), "=r"((r)[3]) : "r"(addr))
#define LDSM_X4T(r, addr) \
    asm volatile("ldmatrix.sync.aligned.m8n8.x4.trans.shared.b16 {%0,%1,%2,%3}, [%4];" \
        : "=r"((r)[0]), "=r"((r)[1]), "=r"((r)[2]), "=r"((r)[3]) : "r"(addr))

__device__ __forceinline__ void mma16816h(float* d, const uint32_t* a, const uint32_t* b) {
    asm volatile(
        "mma.sync.aligned.m16n8k16.row.col.f32.f16.f16.f32 "
        "{%0,%1,%2,%3}, {%4,%5,%6,%7}, {%8,%9}, {%0,%1,%2,%3};"
        : "+f"(d[0]), "+f"(d[1]), "+f"(d[2]), "+f"(d[3])
        : "r"(a[0]), "r"(a[1]), "r"(a[2]), "r"(a[3]), "r"(b[0]), "r"(b[1]));
}

// ---------------- K0: fused prep (+ zeroing of g_updf and d_out) --------------
__global__ void k_prep(const float* __restrict__ Wqkv, const float* __restrict__ Wro,
                       const float* __restrict__ Wtp, const int* __restrict__ batch,
                       float* __restrict__ out) {
    int bid = blockIdx.x;
    int tid = threadIdx.x;       // 256
    if (bid < 48) {
        __shared__ float srow[4][64];
        int rr = tid >> 6, m = tid & 63;
        int r = bid * 4 + rr;
        srow[rr][m] = Wqkv[r * H_ + m];
        __syncthreads();
        float s = 0.f;
#pragma unroll 8
        for (int u = 0; u < H_; u++) s += srow[rr][u] * Wro[u * H_ + m];
        g_A[m * TH_ + r] = s;
    } else if (bid < 112) {
        int i = bid - 48;
        __shared__ float s[64 * 65];
#pragma unroll
        for (int p = 0; p < 16; p++) {
            int l = p * 256 + tid;
            int k = l >> 6, j = l & 63;
            s[k * 65 + j] = Wtp[k * 4096 + i * 64 + j];
        }
        __syncthreads();
#pragma unroll
        for (int p = 0; p < 16; p++) {
            int l = p * 256 + tid;
            int j = l >> 6, k = l & 63;
            g_B16[i * 4096 + j * 64 + k] = __float2half_rn(s[k * 65 + j]);
        }
    } else if (bid == 112) {
        if (tid <= G_) {
            int lo = 0, hi = N_;
            while (lo < hi) {
                int mid = (lo + hi) >> 1;
                if (batch[mid] < tid) lo = mid + 1; else hi = mid;
            }
            g_seg[tid] = lo;
        }
    } else if (bid < 129) {
        float4* dst = (float4*)g_updf + (bid - 113) * 4096;
#pragma unroll
        for (int p = 0; p < 16; p++) dst[p * 256 + tid] = make_float4(0.f, 0.f, 0.f, 0.f);
    } else {
        float4* dst = (float4*)out + (bid - 129) * 4096;
#pragma unroll
        for (int p = 0; p < 16; p++) dst[p * 256 + tid] = make_float4(0.f, 0.f, 0.f, 0.f);
    }
}

// ---------------- K1: qkv tiled GEMM (32 nodes/block) + silu + rope -----------
#define QKV_SA   0
#define QKV_NF   49152
#define QKV_QKV  58368
#define QKV_C    83968
#define QKV_S    84992
#define QKV_SMEM 86016

__global__ void __launch_bounds__(256) k_qkv(const float* __restrict__ node_feat,
                                             const float* __restrict__ positions,
                                             const float* __restrict__ kvecs,
                                             const int*   __restrict__ batch) {
    extern __shared__ char sm[];
    float* s_A   = (float*)(sm + QKV_SA);
    float* s_nfT = (float*)(sm + QKV_NF);
    float* s_qkv = (float*)(sm + QKV_QKV);
    float* s_c   = (float*)(sm + QKV_C);
    float* s_s   = (float*)(sm + QKV_S);
    int tid = threadIdx.x;       // 256
    int n0 = blockIdx.x * 32;

#pragma unroll
    for (int p = 0; p < 48; p++) s_A[p * 256 + tid] = g_A[p * 256 + tid];
#pragma unroll
    for (int p = 0; p < 8; p++) {
        int l = p * 256 + tid;
        int nn = l >> 6, k = l & 63;
        s_nfT[k * 36 + nn] = node_feat[(n0 + nn) * H_ + k];
    }
    __syncthreads();

    int tn = tid >> 5, tr = tid & 31;
    float acc[4][6];
#pragma unroll
    for (int nn = 0; nn < 4; nn++)
#pragma unroll
        for (int u = 0; u < 6; u++) acc[nn][u] = 0.f;

#pragma unroll 4
    for (int k = 0; k < 64; k++) {
        float4 nf4 = *(const float4*)&s_nfT[k * 36 + tn * 4];
        float av[6];
#pragma unroll
        for (int u = 0; u < 6; u++) av[u] = s_A[k * 192 + tr + 32 * u];
#pragma unroll
        for (int u = 0; u < 6; u++) {
            acc[0][u] += nf4.x * av[u];
            acc[1][u] += nf4.y * av[u];
            acc[2][u] += nf4.z * av[u];
            acc[3][u] += nf4.w * av[u];
        }
    }
    __syncthreads();

#pragma unroll
    for (int nn = 0; nn < 4; nn++) {
        int node = tn * 4 + nn;
#pragma unroll
        for (int u = 0; u < 6; u++) {
            int r = tr + 32 * u;
            float v = acc[nn][u];
            if (r < 2 * H_) v = v / (1.f + __expf(-v));
            s_qkv[node * 200 + r] = v;
        }
    }
    if (tid < 192) {
        int nn = tid / 6, t = tid % 6;
        int g = batch[n0 + nn];
        const float* kv = kvecs + (g * T_ + t) * 3;
        float ph = positions[(n0 + nn) * 3 + 0] * kv[0]
                 + positions[(n0 + nn) * 3 + 1] * kv[1]
                 + positions[(n0 + nn) * 3 + 2] * kv[2];
        float sv, cv;
        sincosf(ph, &sv, &cv);
        s_c[nn * 8 + t] = cv; s_s[nn * 8 + t] = sv;
    }
    __syncthreads();

#pragma unroll
    for (int p = 0; p < 48; p++) {
        int l = p * 256 + tid;
        int nn = l / 384, idx = l - nn * 384;
        int t = idx >> 6, d = idx & 63;
        int m2 = (d & 31) * 2;
        float c = s_c[nn * 8 + t], sv = s_s[nn * 8 + t];
        float qa = s_qkv[nn * 200 + m2],       qb = s_qkv[nn * 200 + m2 + 1];
        float ka = s_qkv[nn * 200 + 64 + m2],  kb = s_qkv[nn * 200 + 64 + m2 + 1];
        float qv, kvv;
        if (d < 32) { qv = qa * c  - qb * sv;  kvv = ka * c  - kb * sv; }
        else        { qv = qa * sv + qb * c;   kvv = ka * sv + kb * c;  }
        int n = n0 + nn;
        g_qr16[n * TD_ + idx] = __float2half_rn(qv * 0.125f);
        g_k16 [n * TD_ + idx] = __float2half_rn(kvv);
    }
#pragma unroll
    for (int p = 0; p < 8; p++) {
        int l = p * 256 + tid;
        int nn = l >> 6, m = l & 63;
        g_v16[(n0 + nn) * H_ + m] = __float2half_rn(s_qkv[nn * 200 + 128 + m]);
    }
}

// ---------------- K2: FUSED kv_graph + update, per (g,t) block ----------------
#define KU_KT   0        // phase1 kT: 64 x 144 = 9216 ; phase2: reused as TILE
#define KU_V    9216     // phase1 v : 64 x 144 = 9216 ; phase2: reused as Q
#define KU_SMEM 18432

__global__ void __launch_bounds__(256) k_kvgupd() {
    __shared__ __align__(16) char sm[KU_SMEM];
    uint32_t sb = smem_u32(sm);
    int bid = blockIdx.x;
    int g = bid / T_, t = bid % T_;
    int tid = threadIdx.x;
    int lane = tid & 31, w = tid >> 5;
    int wm = w & 3, wn = w >> 2;          // phase1: m16 of d, e32 half

    int s = g_seg[g], e = g_seg[g + 1];
    int nb0 = s & ~63;

    int rfr = (lane & 7) + ((lane >> 3) & 1) * 8;
    int cfr = (lane >> 4) * 16;

    float acc[4][4];
#pragma unroll
    for (int nt = 0; nt < 4; nt++)
#pragma unroll
        for (int q = 0; q < 4; q++) acc[nt][q] = 0.f;

    int pp = tid & 31, oo = tid >> 5;     // n-pair 0..31, d-oct 0..7

    // ===== Phase 1: kv_graph tile =====
    for (int nb = nb0; nb < e; nb += 64) {
        int n1 = nb + 2 * pp, n2 = n1 + 1;
        uint4 ra = make_uint4(0u,0u,0u,0u), rb = ra;
        if (n1 >= s && n1 < e) ra = *(const uint4*)(g_k16 + n1 * TD_ + t * 64 + oo * 8);
        if (n2 >= s && n2 < e) rb = *(const uint4*)(g_k16 + n2 * TD_ + t * 64 + oo * 8);
        const __half* ah = (const __half*)&ra;
        const __half* bh = (const __half*)&rb;
#pragma unroll
        for (int dd = 0; dd < 8; dd++) {
            __half2 h = __halves2half2(ah[dd], bh[dd]);
            *(__half2*)(sm + KU_KT + (oo * 8 + dd) * RSTRIDE + pp * 4) = h;
        }
#pragma unroll
        for (int p = 0; p < 2; p++) {
            int idx = p * 256 + tid;
            int r = idx >> 3, q8 = idx & 7;
            int n = nb + r;
            uint4 val = make_uint4(0u, 0u, 0u, 0u);
            if (n >= s && n < e) val = *(const uint4*)(g_v16 + n * H_ + q8 * 8);
            *(uint4*)(sm + KU_V + r * RSTRIDE + q8 * 16) = val;
        }
        __syncthreads();

#pragma unroll
        for (int ks = 0; ks < 4; ks++) {
            uint32_t aF[4], bF[8];
            LDSM_X4(aF, sb + KU_KT + (uint32_t)(wm * 16 + rfr) * RSTRIDE + cfr + ks * 32);
            LDSM_X4T(&bF[0], sb + KU_V + (uint32_t)(ks * 16 + rfr) * RSTRIDE + wn * 64 + cfr);
            LDSM_X4T(&bF[4], sb + KU_V + (uint32_t)(ks * 16 + rfr) * RSTRIDE + wn * 64 + 32 + cfr);
            mma16816h(acc[0], aF, &bF[0]);
            mma16816h(acc[1], aF, &bF[2]);
            mma16816h(acc[2], aF, &bF[4]);
            mma16816h(acc[3], aF, &bF[6]);
        }
        __syncthreads();
    }

    // ===== write tile to smem fp16 (reuse KU_KT region: [64 d rows][64 e]) =====
    {
        int d0 = wm * 16 + (lane >> 2);
        int cb = 2 * (lane & 3);
#pragma unroll
        for (int nt = 0; nt < 4; nt++) {
            int ec = wn * 32 + nt * 8 + cb;
            *(__half2*)(sm + KU_KT + d0 * RSTRIDE + ec * 2) =
                __floats2half2_rn(acc[nt][0], acc[nt][1]);
            *(__half2*)(sm + KU_KT + (d0 + 8) * RSTRIDE + ec * 2) =
                __floats2half2_rn(acc[nt][2], acc[nt][3]);
        }
    }
    __syncthreads();

    // ===== Phase 2: updf[n,e] += q[n, t*64: ] @ tile, per 64-node chunk =====
    int weg = wn;
    for (int nb = nb0; nb < e; nb += 64) {
#pragma unroll
        for (int p = 0; p < 2; p++) {
            int idx = p * 256 + tid;
            int nl = idx >> 3, q8 = idx & 7;
            int n = nb + nl;
            uint4 val = make_uint4(0u, 0u, 0u, 0u);
            if (n >= s && n < e) val = *(const uint4*)(g_qr16 + n * TD_ + t * 64 + q8 * 8);
            *(uint4*)(sm + KU_V + nl * RSTRIDE + q8 * 16) = val;
        }
        __syncthreads();

        float pacc[4][4];
#pragma unroll
        for (int nt = 0; nt < 4; nt++)
#pragma unroll
            for (int q = 0; q < 4; q++) pacc[nt][q] = 0.f;

        uint32_t aB = sb + KU_V  + (uint32_t)(wm * 16 + rfr) * RSTRIDE + cfr;
        uint32_t bB = sb + KU_KT + (uint32_t)rfr * RSTRIDE + weg * 64 + cfr;
#pragma unroll
        for (int ks = 0; ks < 4; ks++) {
            uint32_t aF[4], bF[8];
            LDSM_X4(aF, aB + ks * 32);
            LDSM_X4T(&bF[0], bB + ks * (16 * RSTRIDE));
            LDSM_X4T(&bF[4], bB + ks * (16 * RSTRIDE) + 32);
            mma16816h(pacc[0], aF, &bF[0]);
            mma16816h(pacc[1], aF, &bF[2]);
            mma16816h(pacc[2], aF, &bF[4]);
            mma16816h(pacc[3], aF, &bF[6]);
        }

        int r0 = wm * 16 + (lane >> 2);
        int cb = 2 * (lane & 3);
        int n1 = nb + r0, n2 = n1 + 8;
#pragma unroll
        for (int nt = 0; nt < 4; nt++) {
            int ec = weg * 32 + nt * 8 + cb;
            if (n1 >= s && n1 < e) {
                atomicAdd(&g_updf[n1 * H_ + ec],     pacc[nt][0]);
                atomicAdd(&g_updf[n1 * H_ + ec + 1], pacc[nt][1]);
            }
            if (n2 >= s && n2 < e) {
                atomicAdd(&g_updf[n2 * H_ + ec],     pacc[nt][2]);
                atomicAdd(&g_updf[n2 * H_ + ec + 1], pacc[nt][3]);
            }
        }
        __syncthreads();
    }
}

// ---------------- K3: tensor-product GEMM, 4m x 2n warp tiling ----------------
// warps: wm (0..3) -> rows wm*32..+31 (2 m16 tiles); wn (0..1) -> cols wn*32..+31
#define TP_U    0
#define TP_B0   18432
#define TP_B1   27648
#define TP_NF   36864
#define TP_SMEM 41984

__global__ void __launch_bounds__(256, 2) k_tpmma(const float* __restrict__ nfsr,
                                                  float* __restrict__ out) {
    extern __shared__ char smem[];
    uint32_t sb = smem_u32(smem);
    int tid = threadIdx.x;
    int wid = tid >> 5, lane = tid & 31;
    int n0 = blockIdx.x * 128;
    int i0 = blockIdx.y * 8;
    int wm = wid & 3, wn = wid >> 2;

    float* s_nf = (float*)(smem + TP_NF);     // [c][128], c<8

#pragma unroll
    for (int p = 0; p < 4; p++) {
        int l = p * 256 + tid;                 // 0..1023
        int nl = l >> 3, ii = l & 7;
        s_nf[ii * 128 + nl] = nfsr[(n0 + nl) * H_ + i0 + ii];
    }
    // build fp16 U tile from fp32 g_updf
#pragma unroll
    for (int p = 0; p < 4; p++) {
        int idx = p * 256 + tid;              // 0..1023
        int n = idx >> 3, q8 = idx & 7;
        const float4* src = (const float4*)(g_updf + (n0 + n) * H_ + q8 * 8);
        float4 u0 = src[0], u1 = src[1];
        __half2 h0 = __floats2half2_rn(u0.x, u0.y);
        __half2 h1 = __floats2half2_rn(u0.z, u0.w);
        __half2 h2 = __floats2half2_rn(u1.x, u1.y);
        __half2 h3 = __floats2half2_rn(u1.z, u1.w);
        uint4 val = make_uint4(*(uint32_t*)&h0, *(uint32_t*)&h1,
                               *(uint32_t*)&h2, *(uint32_t*)&h3);
        *(uint4*)(smem + TP_U + n * RSTRIDE + q8 * 16) = val;
    }
    {
        const uint4* bs = (const uint4*)(g_B16 + i0 * 4096);
        uint4 b0 = bs[tid], b1 = bs[tid + 256];
        int q = tid & 7;
        int ja = tid >> 3, jb = (tid + 256) >> 3;
        *(uint4*)(smem + TP_B0 + ja * RSTRIDE + q * 16) = b0;
        *(uint4*)(smem + TP_B0 + jb * RSTRIDE + q * 16) = b1;
    }
    __syncthreads();

    int rfr = (lane & 7) + ((lane >> 3) & 1) * 8;
    int cfr = (lane >> 4) * 16;

    // resident A fragments: 2 m16 tiles x 4 k-steps
    uint32_t aF[32];
#pragma unroll
    for (int mt = 0; mt < 2; mt++) {
        uint32_t aAddr = sb + TP_U + (uint32_t)(wm * 32 + mt * 16 + rfr) * RSTRIDE + cfr;
#pragma unroll
        for (int ks = 0; ks < 4; ks++) LDSM_X4(&aF[mt * 16 + ks * 4], aAddr + ks * 32);
    }

    float acc[2][4][4];
#pragma unroll
    for (int mt = 0; mt < 2; mt++)
#pragma unroll
        for (int nt = 0; nt < 4; nt++)
#pragma unroll
            for (int q = 0; q < 4; q++) acc[mt][nt][q] = 0.f;

    int rowl = wm * 32 + (lane >> 2);
    int qb8 = tid & 7;
    int ja = tid >> 3, jb = (tid + 256) >> 3;

    for (int c = 0; c < 8; c++) {
        uint4 pfa, pfb;
        if (c < 7) {
            const uint4* bs = (const uint4*)(g_B16 + (i0 + c + 1) * 4096);
            pfa = bs[tid]; pfb = bs[tid + 256];
        }

        uint32_t bBase = sb + ((c & 1) ? TP_B1 : TP_B0)
                       + (uint32_t)rfr * RSTRIDE + wn * 64 + cfr;
        float ptmp[2][4][4];
#pragma unroll
        for (int mt = 0; mt < 2; mt++)
#pragma unroll
            for (int nt = 0; nt < 4; nt++)
#pragma unroll
                for (int q = 0; q < 4; q++) ptmp[mt][nt][q] = 0.f;

#pragma unroll
        for (int ks = 0; ks < 4; ks++) {
            uint32_t bF[8];
            LDSM_X4T(&bF[0], bBase + ks * (16 * RSTRIDE));
            LDSM_X4T(&bF[4], bBase + ks * (16 * RSTRIDE) + 32);
#pragma unroll
            for (int mt = 0; mt < 2; mt++)
#pragma unroll
                for (int nt = 0; nt < 4; nt++)
                    mma16816h(ptmp[mt][nt], &aF[mt * 16 + ks * 4], &bF[nt * 2]);
        }

#pragma unroll
        for (int mt = 0; mt < 2; mt++) {
            float f0 = s_nf[c * 128 + rowl + mt * 16];
            float f1 = s_nf[c * 128 + rowl + mt * 16 + 8];
#pragma unroll
            for (int nt = 0; nt < 4; nt++) {
                acc[mt][nt][0] += f0 * ptmp[mt][nt][0];
                acc[mt][nt][1] += f0 * ptmp[mt][nt][1];
                acc[mt][nt][2] += f1 * ptmp[mt][nt][2];
                acc[mt][nt][3] += f1 * ptmp[mt][nt][3];
            }
        }

        if (c < 7) {
            char* dst = smem + ((c & 1) ? TP_B0 : TP_B1);
            *(uint4*)(dst + ja * RSTRIDE + qb8 * 16) = pfa;
            *(uint4*)(dst + jb * RSTRIDE + qb8 * 16) = pfb;
            __syncthreads();
        }
    }

    int colb = 2 * (lane & 3);
#pragma unroll
    for (int mt = 0; mt < 2; mt++) {
        int row0 = n0 + wm * 32 + mt * 16 + (lane >> 2);
#pragma unroll
        for (int nt = 0; nt < 4; nt++) {
            int col = wn * 32 + nt * 8 + colb;
            atomicAdd(&out[row0 * H_ + col],           acc[mt][nt][0]);
            atomicAdd(&out[row0 * H_ + col + 1],       acc[mt][nt][1]);
            atomicAdd(&out[(row0 + 8) * H_ + col],     acc[mt][nt][2]);
            atomicAdd(&out[(row0 + 8) * H_ + col + 1], acc[mt][nt][3]);
        }
    }
}

// ---------------- launch ----------------
extern "C" void kernel_launch(void* const* d_in, const int* in_sizes, int n_in,
                              void* d_out, int out_size) {
    const float* node_feat    = (const float*)d_in[0];
    const float* node_feat_sr = (const float*)d_in[1];
    const float* positions    = (const float*)d_in[2];
    const float* kvecs        = (const float*)d_in[3];
    const int*   batch        = (const int*)  d_in[4];
    const float* W_readout    = (const float*)d_in[5];
    const float* W_qkv        = (const float*)d_in[6];
    const float* W_tp         = (const float*)d_in[7];
    float* out = (float*)d_out;

    static int attr_done = 0;
    if (!attr_done) {
        cudaFuncSetAttribute(k_qkv, cudaFuncAttributeMaxDynamicSharedMemorySize, QKV_SMEM);
        attr_done = 1;
    }

    k_prep   <<<145, 256>>>(W_qkv, W_readout, W_tp, batch, out);
    k_qkv    <<<N_ / 32, 256, QKV_SMEM>>>(node_feat, positions, kvecs, batch);
    k_kvgupd <<<G_ * T_, 256>>>();
    k_tpmma  <<<dim3(N_ / 128, 8), 256, TP_SMEM>>>(node_feat_sr, out);
}

// round 13
// speedup vs baseline: 1.0333x; 1.0333x over previous
#include <cuda_runtime.h>
#include <cuda_fp16.h>
#include <math.h>
#include <stdint.h>

#define N_  4096
#define H_  64
#define T_  6
#define G_  16
#define TH_ 192    // 3*H
#define TD_ 384    // T*H

// ---------------- device scratch ----------------
__device__ float g_A[H_ * TH_];            // A[m][r] = Wc[r][m]
__device__ __align__(16) __half g_qr16[N_ * TD_];       // q fp16 [n][t*64+d]
__device__ __align__(16) __half g_k16 [N_ * TD_];       // k fp16 [n][t*64+d]
__device__ __align__(16) __half g_v16 [N_ * H_];        // v fp16 [n][e]
__device__ __align__(16) float  g_updf[N_ * H_];        // update fp32 [n][e] (atomic)
__device__ __half g_B16[H_ * H_ * H_];     // W_tp fp16, [i][j][k]
__device__ int   g_seg[G_ + 1];

#define RSTRIDE 144   // 72 fp16 row stride (bytes)

// ---------------- PTX helpers ----------------
__device__ __forceinline__ uint32_t smem_u32(const void* p) {
    uint32_t a;
    asm("{ .reg .u64 t; cvta.to.shared.u64 t, %1; cvt.u32.u64 %0, t; }" : "=r"(a) : "l"(p));
    return a;
}
#define LDSM_X4(r, addr) \
    asm volatile("ldmatrix.sync.aligned.m8n8.x4.shared.b16 {%0,%1,%2,%3}, [%4];" \
        : "=r"((r)[0]), "=r"((r)[1]), "=r"((r)[2]), "=r"((r)[3]) : "r"(addr))
#define LDSM_X4T(r, addr) \
    asm volatile("ldmatrix.sync.aligned.m8n8.x4.trans.shared.b16 {%0,%1,%2,%3}, [%4];" \
        : "=r"((r)[0]), "=r"((r)[1]), "=r"((r)[2]), "=r"((r)[3]) : "r"(addr))

__device__ __forceinline__ void mma16816h(float* d, const uint32_t* a, const uint32_t* b) {
    asm volatile(
        "mma.sync.aligned.m16n8k16.row.col.f32.f16.f16.f32 "
        "{%0,%1,%2,%3}, {%4,%5,%6,%7}, {%8,%9}, {%0,%1,%2,%3};"
        : "+f"(d[0]), "+f"(d[1]), "+f"(d[2]), "+f"(d[3])
        : "r"(a[0]), "r"(a[1]), "r"(a[2]), "r"(a[3]), "r"(b[0]), "r"(b[1]));
}

// ---------------- K0: fused prep (+ zeroing of g_updf and d_out) --------------
__global__ void k_prep(const float* __restrict__ Wqkv, const float* __restrict__ Wro,
                       const float* __restrict__ Wtp, const int* __restrict__ batch,
                       float* __restrict__ out) {
    int bid = blockIdx.x;
    int tid = threadIdx.x;       // 256
    if (bid < 48) {
        __shared__ float srow[4][64];
        int rr = tid >> 6, m = tid & 63;
        int r = bid * 4 + rr;
        srow[rr][m] = Wqkv[r * H_ + m];
        __syncthreads();
        float s = 0.f;
#pragma unroll 8
        for (int u = 0; u < H_; u++) s += srow[rr][u] * Wro[u * H_ + m];
        g_A[m * TH_ + r] = s;
    } else if (bid < 112) {
        int i = bid - 48;
        __shared__ float s[64 * 65];
#pragma unroll
        for (int p = 0; p < 16; p++) {
            int l = p * 256 + tid;
            int k = l >> 6, j = l & 63;
            s[k * 65 + j] = Wtp[k * 4096 + i * 64 + j];
        }
        __syncthreads();
#pragma unroll
        for (int p = 0; p < 16; p++) {
            int l = p * 256 + tid;
            int j = l >> 6, k = l & 63;
            g_B16[i * 4096 + j * 64 + k] = __float2half_rn(s[k * 65 + j]);
        }
    } else if (bid == 112) {
        if (tid <= G_) {
            int lo = 0, hi = N_;
            while (lo < hi) {
                int mid = (lo + hi) >> 1;
                if (batch[mid] < tid) lo = mid + 1; else hi = mid;
            }
            g_seg[tid] = lo;
        }
    } else if (bid < 129) {
        float4* dst = (float4*)g_updf + (bid - 113) * 4096;
#pragma unroll
        for (int p = 0; p < 16; p++) dst[p * 256 + tid] = make_float4(0.f, 0.f, 0.f, 0.f);
    } else {
        float4* dst = (float4*)out + (bid - 129) * 4096;
#pragma unroll
        for (int p = 0; p < 16; p++) dst[p * 256 + tid] = make_float4(0.f, 0.f, 0.f, 0.f);
    }
}

// ---------------- K1: qkv tiled GEMM (32 nodes/block) + silu + rope -----------
#define QKV_SA   0
#define QKV_NF   49152
#define QKV_QKV  58368
#define QKV_C    83968
#define QKV_S    84992
#define QKV_SMEM 86016

__global__ void __launch_bounds__(256) k_qkv(const float* __restrict__ node_feat,
                                             const float* __restrict__ positions,
                                             const float* __restrict__ kvecs,
                                             const int*   __restrict__ batch) {
    extern __shared__ char sm[];
    float* s_A   = (float*)(sm + QKV_SA);
    float* s_nfT = (float*)(sm + QKV_NF);
    float* s_qkv = (float*)(sm + QKV_QKV);
    float* s_c   = (float*)(sm + QKV_C);
    float* s_s   = (float*)(sm + QKV_S);
    int tid = threadIdx.x;       // 256
    int n0 = blockIdx.x * 32;

#pragma unroll
    for (int p = 0; p < 48; p++) s_A[p * 256 + tid] = g_A[p * 256 + tid];
#pragma unroll
    for (int p = 0; p < 8; p++) {
        int l = p * 256 + tid;
        int nn = l >> 6, k = l & 63;
        s_nfT[k * 36 + nn] = node_feat[(n0 + nn) * H_ + k];
    }
    __syncthreads();

    int tn = tid >> 5, tr = tid & 31;
    float acc[4][6];
#pragma unroll
    for (int nn = 0; nn < 4; nn++)
#pragma unroll
        for (int u = 0; u < 6; u++) acc[nn][u] = 0.f;

#pragma unroll 4
    for (int k = 0; k < 64; k++) {
        float4 nf4 = *(const float4*)&s_nfT[k * 36 + tn * 4];
        float av[6];
#pragma unroll
        for (int u = 0; u < 6; u++) av[u] = s_A[k * 192 + tr + 32 * u];
#pragma unroll
        for (int u = 0; u < 6; u++) {
            acc[0][u] += nf4.x * av[u];
            acc[1][u] += nf4.y * av[u];
            acc[2][u] += nf4.z * av[u];
            acc[3][u] += nf4.w * av[u];
        }
    }
    __syncthreads();

#pragma unroll
    for (int nn = 0; nn < 4; nn++) {
        int node = tn * 4 + nn;
#pragma unroll
        for (int u = 0; u < 6; u++) {
            int r = tr + 32 * u;
            float v = acc[nn][u];
            if (r < 2 * H_) v = v / (1.f + __expf(-v));
            s_qkv[node * 200 + r] = v;
        }
    }
    if (tid < 192) {
        int nn = tid / 6, t = tid % 6;
        int g = batch[n0 + nn];
        const float* kv = kvecs + (g * T_ + t) * 3;
        float ph = positions[(n0 + nn) * 3 + 0] * kv[0]
                 + positions[(n0 + nn) * 3 + 1] * kv[1]
                 + positions[(n0 + nn) * 3 + 2] * kv[2];
        float sv, cv;
        sincosf(ph, &sv, &cv);
        s_c[nn * 8 + t] = cv; s_s[nn * 8 + t] = sv;
    }
    __syncthreads();

#pragma unroll
    for (int p = 0; p < 48; p++) {
        int l = p * 256 + tid;
        int nn = l / 384, idx = l - nn * 384;
        int t = idx >> 6, d = idx & 63;
        int m2 = (d & 31) * 2;
        float c = s_c[nn * 8 + t], sv = s_s[nn * 8 + t];
        float qa = s_qkv[nn * 200 + m2],       qb = s_qkv[nn * 200 + m2 + 1];
        float ka = s_qkv[nn * 200 + 64 + m2],  kb = s_qkv[nn * 200 + 64 + m2 + 1];
        float qv, kvv;
        if (d < 32) { qv = qa * c  - qb * sv;  kvv = ka * c  - kb * sv; }
        else        { qv = qa * sv + qb * c;   kvv = ka * sv + kb * c;  }
        int n = n0 + nn;
        g_qr16[n * TD_ + idx] = __float2half_rn(qv * 0.125f);
        g_k16 [n * TD_ + idx] = __float2half_rn(kvv);
    }
#pragma unroll
    for (int p = 0; p < 8; p++) {
        int l = p * 256 + tid;
        int nn = l >> 6, m = l & 63;
        g_v16[(n0 + nn) * H_ + m] = __float2half_rn(s_qkv[nn * 200 + 128 + m]);
    }
}

// ---------------- K2: FUSED kv_graph + update, per (g,t) block ----------------
#define KU_KT   0        // phase1 kT: 64 x 144 = 9216 ; phase2: reused as TILE
#define KU_V    9216     // phase1 v : 64 x 144 = 9216 ; phase2: reused as Q
#define KU_SMEM 18432

__global__ void __launch_bounds__(256) k_kvgupd() {
    __shared__ __align__(16) char sm[KU_SMEM];
    uint32_t sb = smem_u32(sm);
    int bid = blockIdx.x;
    int g = bid / T_, t = bid % T_;
    int tid = threadIdx.x;
    int lane = tid & 31, w = tid >> 5;
    int wm = w & 3, wn = w >> 2;          // phase1: m16 of d, e32 half

    int s = g_seg[g], e = g_seg[g + 1];
    int nb0 = s & ~63;

    int rfr = (lane & 7) + ((lane >> 3) & 1) * 8;
    int cfr = (lane >> 4) * 16;

    float acc[4][4];
#pragma unroll
    for (int nt = 0; nt < 4; nt++)
#pragma unroll
        for (int q = 0; q < 4; q++) acc[nt][q] = 0.f;

    int pp = tid & 31, oo = tid >> 5;     // n-pair 0..31, d-oct 0..7

    // ===== Phase 1: kv_graph tile =====
    for (int nb = nb0; nb < e; nb += 64) {
        int n1 = nb + 2 * pp, n2 = n1 + 1;
        uint4 ra = make_uint4(0u,0u,0u,0u), rb = ra;
        if (n1 >= s && n1 < e) ra = *(const uint4*)(g_k16 + n1 * TD_ + t * 64 + oo * 8);
        if (n2 >= s && n2 < e) rb = *(const uint4*)(g_k16 + n2 * TD_ + t * 64 + oo * 8);
        const __half* ah = (const __half*)&ra;
        const __half* bh = (const __half*)&rb;
#pragma unroll
        for (int dd = 0; dd < 8; dd++) {
            __half2 h = __halves2half2(ah[dd], bh[dd]);
            *(__half2*)(sm + KU_KT + (oo * 8 + dd) * RSTRIDE + pp * 4) = h;
        }
#pragma unroll
        for (int p = 0; p < 2; p++) {
            int idx = p * 256 + tid;
            int r = idx >> 3, q8 = idx & 7;
            int n = nb + r;
            uint4 val = make_uint4(0u, 0u, 0u, 0u);
            if (n >= s && n < e) val = *(const uint4*)(g_v16 + n * H_ + q8 * 8);
            *(uint4*)(sm + KU_V + r * RSTRIDE + q8 * 16) = val;
        }
        __syncthreads();

#pragma unroll
        for (int ks = 0; ks < 4; ks++) {
            uint32_t aF[4], bF[8];
            LDSM_X4(aF, sb + KU_KT + (uint32_t)(wm * 16 + rfr) * RSTRIDE + cfr + ks * 32);
            LDSM_X4T(&bF[0], sb + KU_V + (uint32_t)(ks * 16 + rfr) * RSTRIDE + wn * 64 + cfr);
            LDSM_X4T(&bF[4], sb + KU_V + (uint32_t)(ks * 16 + rfr) * RSTRIDE + wn * 64 + 32 + cfr);
            mma16816h(acc[0], aF, &bF[0]);
            mma16816h(acc[1], aF, &bF[2]);
            mma16816h(acc[2], aF, &bF[4]);
            mma16816h(acc[3], aF, &bF[6]);
        }
        __syncthreads();
    }

    // ===== write tile to smem fp16 (reuse KU_KT region: [64 d rows][64 e]) =====
    {
        int d0 = wm * 16 + (lane >> 2);
        int cb = 2 * (lane & 3);
#pragma unroll
        for (int nt = 0; nt < 4; nt++) {
            int ec = wn * 32 + nt * 8 + cb;
            *(__half2*)(sm + KU_KT + d0 * RSTRIDE + ec * 2) =
                __floats2half2_rn(acc[nt][0], acc[nt][1]);
            *(__half2*)(sm + KU_KT + (d0 + 8) * RSTRIDE + ec * 2) =
                __floats2half2_rn(acc[nt][2], acc[nt][3]);
        }
    }
    __syncthreads();

    // ===== Phase 2: updf[n,e] += q[n, t*64: ] @ tile, per 64-node chunk =====
    int weg = wn;
    for (int nb = nb0; nb < e; nb += 64) {
#pragma unroll
        for (int p = 0; p < 2; p++) {
            int idx = p * 256 + tid;
            int nl = idx >> 3, q8 = idx & 7;
            int n = nb + nl;
            uint4 val = make_uint4(0u, 0u, 0u, 0u);
            if (n >= s && n < e) val = *(const uint4*)(g_qr16 + n * TD_ + t * 64 + q8 * 8);
            *(uint4*)(sm + KU_V + nl * RSTRIDE + q8 * 16) = val;
        }
        __syncthreads();

        float pacc[4][4];
#pragma unroll
        for (int nt = 0; nt < 4; nt++)
#pragma unroll
            for (int q = 0; q < 4; q++) pacc[nt][q] = 0.f;

        uint32_t aB = sb + KU_V  + (uint32_t)(wm * 16 + rfr) * RSTRIDE + cfr;
        uint32_t bB = sb + KU_KT + (uint32_t)rfr * RSTRIDE + weg * 64 + cfr;
#pragma unroll
        for (int ks = 0; ks < 4; ks++) {
            uint32_t aF[4], bF[8];
            LDSM_X4(aF, aB + ks * 32);
            LDSM_X4T(&bF[0], bB + ks * (16 * RSTRIDE));
            LDSM_X4T(&bF[4], bB + ks * (16 * RSTRIDE) + 32);
            mma16816h(pacc[0], aF, &bF[0]);
            mma16816h(pacc[1], aF, &bF[2]);
            mma16816h(pacc[2], aF, &bF[4]);
            mma16816h(pacc[3], aF, &bF[6]);
        }

        int r0 = wm * 16 + (lane >> 2);
        int cb = 2 * (lane & 3);
        int n1 = nb + r0, n2 = n1 + 8;
#pragma unroll
        for (int nt = 0; nt < 4; nt++) {
            int ec = weg * 32 + nt * 8 + cb;
            if (n1 >= s && n1 < e) {
                atomicAdd(&g_updf[n1 * H_ + ec],     pacc[nt][0]);
                atomicAdd(&g_updf[n1 * H_ + ec + 1], pacc[nt][1]);
            }
            if (n2 >= s && n2 < e) {
                atomicAdd(&g_updf[n2 * H_ + ec],     pacc[nt][2]);
                atomicAdd(&g_updf[n2 * H_ + ec + 1], pacc[nt][3]);
            }
        }
        __syncthreads();
    }
}

// ---------------- K3: tensor-product GEMM, 4m x 2n warp tiling ----------------
// A fragments pre-scaled per chunk in fp16 (no fp32 staging temp -> no spills)
#define TP_U    0
#define TP_B0   18432
#define TP_B1   27648
#define TP_NF   36864
#define TP_SMEM 41984

__global__ void __launch_bounds__(256, 2) k_tpmma(const float* __restrict__ nfsr,
                                                  float* __restrict__ out) {
    extern __shared__ char smem[];
    uint32_t sb = smem_u32(smem);
    int tid = threadIdx.x;
    int wid = tid >> 5, lane = tid & 31;
    int n0 = blockIdx.x * 128;
    int i0 = blockIdx.y * 8;
    int wm = wid & 3, wn = wid >> 2;

    float* s_nf = (float*)(smem + TP_NF);     // [c][128], c<8

#pragma unroll
    for (int p = 0; p < 4; p++) {
        int l = p * 256 + tid;                 // 0..1023
        int nl = l >> 3, ii = l & 7;
        s_nf[ii * 128 + nl] = nfsr[(n0 + nl) * H_ + i0 + ii];
    }
    // build fp16 U tile from fp32 g_updf
#pragma unroll
    for (int p = 0; p < 4; p++) {
        int idx = p * 256 + tid;              // 0..1023
        int n = idx >> 3, q8 = idx & 7;
        const float4* src = (const float4*)(g_updf + (n0 + n) * H_ + q8 * 8);
        float4 u0 = src[0], u1 = src[1];
        __half2 h0 = __floats2half2_rn(u0.x, u0.y);
        __half2 h1 = __floats2half2_rn(u0.z, u0.w);
        __half2 h2 = __floats2half2_rn(u1.x, u1.y);
        __half2 h3 = __floats2half2_rn(u1.z, u1.w);
        uint4 val = make_uint4(*(uint32_t*)&h0, *(uint32_t*)&h1,
                               *(uint32_t*)&h2, *(uint32_t*)&h3);
        *(uint4*)(smem + TP_U + n * RSTRIDE + q8 * 16) = val;
    }
    {
        const uint4* bs = (const uint4*)(g_B16 + i0 * 4096);
        uint4 b0 = bs[tid], b1 = bs[tid + 256];
        int q = tid & 7;
        int ja = tid >> 3, jb = (tid + 256) >> 3;
        *(uint4*)(smem + TP_B0 + ja * RSTRIDE + q * 16) = b0;
        *(uint4*)(smem + TP_B0 + jb * RSTRIDE + q * 16) = b1;
    }
    __syncthreads();

    int rfr = (lane & 7) + ((lane >> 3) & 1) * 8;
    int cfr = (lane >> 4) * 16;

    // resident A fragments: 2 m16 tiles x 4 k-steps (fp16 upd)
    uint32_t aF[32];
#pragma unroll
    for (int mt = 0; mt < 2; mt++) {
        uint32_t aAddr = sb + TP_U + (uint32_t)(wm * 32 + mt * 16 + rfr) * RSTRIDE + cfr;
#pragma unroll
        for (int ks = 0; ks < 4; ks++) LDSM_X4(&aF[mt * 16 + ks * 4], aAddr + ks * 32);
    }

    float acc[2][4][4];
#pragma unroll
    for (int mt = 0; mt < 2; mt++)
#pragma unroll
        for (int nt = 0; nt < 4; nt++)
#pragma unroll
            for (int q = 0; q < 4; q++) acc[mt][nt][q] = 0.f;

    int rowl = wm * 32 + (lane >> 2);
    int qb8 = tid & 7;
    int ja = tid >> 3, jb = (tid + 256) >> 3;

    for (int c = 0; c < 8; c++) {
        uint4 pfa, pfb;
        if (c < 7) {
            const uint4* bs = (const uint4*)(g_B16 + (i0 + c + 1) * 4096);
            pfa = bs[tid]; pfb = bs[tid + 256];
        }

        uint32_t bBase = sb + ((c & 1) ? TP_B1 : TP_B0)
                       + (uint32_t)rfr * RSTRIDE + wn * 64 + cfr;

#pragma unroll
        for (int ks = 0; ks < 4; ks++) {
            uint32_t bF[8];
            LDSM_X4T(&bF[0], bBase + ks * (16 * RSTRIDE));
            LDSM_X4T(&bF[4], bBase + ks * (16 * RSTRIDE) + 32);
#pragma unroll
            for (int mt = 0; mt < 2; mt++) {
                // pre-scale A fragment by nf factor (rows r0 / r0+8) in fp16
                __half2 f0 = __float2half2_rn(s_nf[c * 128 + rowl + mt * 16]);
                __half2 f1 = __float2half2_rn(s_nf[c * 128 + rowl + mt * 16 + 8]);
                uint32_t sF[4];
                const uint32_t* a4 = &aF[mt * 16 + ks * 4];
                __half2 s0 = __hmul2(*(const __half2*)&a4[0], f0);
                __half2 s1 = __hmul2(*(const __half2*)&a4[1], f1);
                __half2 s2 = __hmul2(*(const __half2*)&a4[2], f0);
                __half2 s3 = __hmul2(*(const __half2*)&a4[3], f1);
                sF[0] = *(uint32_t*)&s0; sF[1] = *(uint32_t*)&s1;
                sF[2] = *(uint32_t*)&s2; sF[3] = *(uint32_t*)&s3;
#pragma unroll
                for (int nt = 0; nt < 4; nt++)
                    mma16816h(acc[mt][nt], sF, &bF[nt * 2]);
            }
        }

        if (c < 7) {
            char* dst = smem + ((c & 1) ? TP_B0 : TP_B1);
            *(uint4*)(dst + ja * RSTRIDE + qb8 * 16) = pfa;
            *(uint4*)(dst + jb * RSTRIDE + qb8 * 16) = pfb;
            __syncthreads();
        }
    }

    int colb = 2 * (lane & 3);
#pragma unroll
    for (int mt = 0; mt < 2; mt++) {
        int row0 = n0 + wm * 32 + mt * 16 + (lane >> 2);
#pragma unroll
        for (int nt = 0; nt < 4; nt++) {
            int col = wn * 32 + nt * 8 + colb;
            atomicAdd(&out[row0 * H_ + col],           acc[mt][nt][0]);
            atomicAdd(&out[row0 * H_ + col + 1],       acc[mt][nt][1]);
            atomicAdd(&out[(row0 + 8) * H_ + col],     acc[mt][nt][2]);
            atomicAdd(&out[(row0 + 8) * H_ + col + 1], acc[mt][nt][3]);
        }
    }
}

// ---------------- launch ----------------
extern "C" void kernel_launch(void* const* d_in, const int* in_sizes, int n_in,
                              void* d_out, int out_size) {
    const float* node_feat    = (const float*)d_in[0];
    const float* node_feat_sr = (const float*)d_in[1];
    const float* positions    = (const float*)d_in[2];
    const float* kvecs        = (const float*)d_in[3];
    const int*   batch        = (const int*)  d_in[4];
    const float* W_readout    = (const float*)d_in[5];
    const float* W_qkv        = (const float*)d_in[6];
    const float* W_tp         = (const float*)d_in[7];
    float* out = (float*)d_out;

    static int attr_done = 0;
    if (!attr_done) {
        cudaFuncSetAttribute(k_qkv, cudaFuncAttributeMaxDynamicSharedMemorySize, QKV_SMEM);
        attr_done = 1;
    }

    k_prep   <<<145, 256>>>(W_qkv, W_readout, W_tp, batch, out);
    k_qkv    <<<N_ / 32, 256, QKV_SMEM>>>(node_feat, positions, kvecs, batch);
    k_kvgupd <<<G_ * T_, 256>>>();
    k_tpmma  <<<dim3(N_ / 128, 8), 256, TP_SMEM>>>(node_feat_sr, out);
}

// round 14
// speedup vs baseline: 1.0491x; 1.0153x over previous
#include <cuda_runtime.h>
#include <cuda_fp16.h>
#include <math.h>
#include <stdint.h>

#define N_  4096
#define H_  64
#define T_  6
#define G_  16
#define TH_ 192    // 3*H
#define TD_ 384    // T*H

// ---------------- device scratch ----------------
__device__ float g_A[H_ * TH_];            // A[m][r] = Wc[r][m]
__device__ __align__(16) __half g_qr16[N_ * TD_];       // q fp16 [n][t*64+d]
__device__ __align__(16) __half g_k16 [N_ * TD_];       // k fp16 [n][t*64+d]
__device__ __align__(16) __half g_v16 [N_ * H_];        // v fp16 [n][e]
__device__ __align__(16) float  g_updf[N_ * H_];        // update fp32 [n][e] (atomic)
// W_tp fp16 in MMA B-fragment order: [i][wn][ks][lane][nt][reg] (uint32 units)
__device__ __align__(16) uint32_t g_Bf[H_ * 2048];
__device__ int   g_seg[G_ + 1];

#define RSTRIDE 144   // 72 fp16 row stride (bytes)

// ---------------- PTX helpers ----------------
__device__ __forceinline__ uint32_t smem_u32(const void* p) {
    uint32_t a;
    asm("{ .reg .u64 t; cvta.to.shared.u64 t, %1; cvt.u32.u64 %0, t; }" : "=r"(a) : "l"(p));
    return a;
}
#define LDSM_X4(r, addr) \
    asm volatile("ldmatrix.sync.aligned.m8n8.x4.shared.b16 {%0,%1,%2,%3}, [%4];" \
        : "=r"((r)[0]), "=r"((r)[1]), "=r"((r)[2]), "=r"((r)[3]) : "r"(addr))
#define LDSM_X4T(r, addr) \
    asm volatile("ldmatrix.sync.aligned.m8n8.x4.trans.shared.b16 {%0,%1,%2,%3}, [%4];" \
        : "=r"((r)[0]), "=r"((r)[1]), "=r"((r)[2]), "=r"((r)[3]) : "r"(addr))

__device__ __forceinline__ void mma16816h(float* d, const uint32_t* a, const uint32_t* b) {
    asm volatile(
        "mma.sync.aligned.m16n8k16.row.col.f32.f16.f16.f32 "
        "{%0,%1,%2,%3}, {%4,%5,%6,%7}, {%8,%9}, {%0,%1,%2,%3};"
        : "+f"(d[0]), "+f"(d[1]), "+f"(d[2]), "+f"(d[3])
        : "r"(a[0]), "r"(a[1]), "r"(a[2]), "r"(a[3]), "r"(b[0]), "r"(b[1]));
}

// ---------------- K0: fused prep (+ zeroing of g_updf and d_out) --------------
__global__ void k_prep(const float* __restrict__ Wqkv, const float* __restrict__ Wro,
                       const float* __restrict__ Wtp, const int* __restrict__ batch,
                       float* __restrict__ out) {
    int bid = blockIdx.x;
    int tid = threadIdx.x;       // 256
    if (bid < 48) {
        __shared__ float srow[4][64];
        int rr = tid >> 6, m = tid & 63;
        int r = bid * 4 + rr;
        srow[rr][m] = Wqkv[r * H_ + m];
        __syncthreads();
        float s = 0.f;
#pragma unroll 8
        for (int u = 0; u < H_; u++) s += srow[rr][u] * Wro[u * H_ + m];
        g_A[m * TH_ + r] = s;
    } else if (bid < 112) {
        int i = bid - 48;
        __shared__ float s[64 * 65];   // s[kout][j] = W_tp[kout][i][j]
#pragma unroll
        for (int p = 0; p < 16; p++) {
            int l = p * 256 + tid;
            int k = l >> 6, j = l & 63;
            s[k * 65 + j] = Wtp[k * 4096 + i * 64 + j];
        }
        __syncthreads();
        // repack into MMA B-fragment order
        int wn = tid >> 7, ks = (tid >> 5) & 3, lane = tid & 31;
        uint32_t w8[8];
#pragma unroll
        for (int nt = 0; nt < 4; nt++)
#pragma unroll
            for (int rg = 0; rg < 2; rg++) {
                int j = ks * 16 + rg * 8 + (lane & 3) * 2;
                int kout = wn * 32 + nt * 8 + (lane >> 2);
                __half2 h = __floats2half2_rn(s[kout * 65 + j], s[kout * 65 + j + 1]);
                w8[nt * 2 + rg] = *(uint32_t*)&h;
            }
        uint32_t base = (uint32_t)((((i * 2 + wn) * 4 + ks) * 32 + lane) << 3);
        *(uint4*)(g_Bf + base)     = make_uint4(w8[0], w8[1], w8[2], w8[3]);
        *(uint4*)(g_Bf + base + 4) = make_uint4(w8[4], w8[5], w8[6], w8[7]);
    } else if (bid == 112) {
        if (tid <= G_) {
            int lo = 0, hi = N_;
            while (lo < hi) {
                int mid = (lo + hi) >> 1;
                if (batch[mid] < tid) lo = mid + 1; else hi = mid;
            }
            g_seg[tid] = lo;
        }
    } else if (bid < 129) {
        float4* dst = (float4*)g_updf + (bid - 113) * 4096;
#pragma unroll
        for (int p = 0; p < 16; p++) dst[p * 256 + tid] = make_float4(0.f, 0.f, 0.f, 0.f);
    } else {
        float4* dst = (float4*)out + (bid - 129) * 4096;
#pragma unroll
        for (int p = 0; p < 16; p++) dst[p * 256 + tid] = make_float4(0.f, 0.f, 0.f, 0.f);
    }
}

// ---------------- K1: qkv tiled GEMM (32 nodes/block) + silu + rope -----------
#define QKV_SA   0
#define QKV_NF   49152
#define QKV_QKV  58368
#define QKV_C    83968
#define QKV_S    84992
#define QKV_SMEM 86016

__global__ void __launch_bounds__(256) k_qkv(const float* __restrict__ node_feat,
                                             const float* __restrict__ positions,
                                             const float* __restrict__ kvecs,
                                             const int*   __restrict__ batch) {
    extern __shared__ char sm[];
    float* s_A   = (float*)(sm + QKV_SA);
    float* s_nfT = (float*)(sm + QKV_NF);
    float* s_qkv = (float*)(sm + QKV_QKV);
    float* s_c   = (float*)(sm + QKV_C);
    float* s_s   = (float*)(sm + QKV_S);
    int tid = threadIdx.x;       // 256
    int n0 = blockIdx.x * 32;

#pragma unroll
    for (int p = 0; p < 48; p++) s_A[p * 256 + tid] = g_A[p * 256 + tid];
#pragma unroll
    for (int p = 0; p < 8; p++) {
        int l = p * 256 + tid;
        int nn = l >> 6, k = l & 63;
        s_nfT[k * 36 + nn] = node_feat[(n0 + nn) * H_ + k];
    }
    __syncthreads();

    int tn = tid >> 5, tr = tid & 31;
    float acc[4][6];
#pragma unroll
    for (int nn = 0; nn < 4; nn++)
#pragma unroll
        for (int u = 0; u < 6; u++) acc[nn][u] = 0.f;

#pragma unroll 4
    for (int k = 0; k < 64; k++) {
        float4 nf4 = *(const float4*)&s_nfT[k * 36 + tn * 4];
        float av[6];
#pragma unroll
        for (int u = 0; u < 6; u++) av[u] = s_A[k * 192 + tr + 32 * u];
#pragma unroll
        for (int u = 0; u < 6; u++) {
            acc[0][u] += nf4.x * av[u];
            acc[1][u] += nf4.y * av[u];
            acc[2][u] += nf4.z * av[u];
            acc[3][u] += nf4.w * av[u];
        }
    }
    __syncthreads();

#pragma unroll
    for (int nn = 0; nn < 4; nn++) {
        int node = tn * 4 + nn;
#pragma unroll
        for (int u = 0; u < 6; u++) {
            int r = tr + 32 * u;
            float v = acc[nn][u];
            if (r < 2 * H_) v = v / (1.f + __expf(-v));
            s_qkv[node * 200 + r] = v;
        }
    }
    if (tid < 192) {
        int nn = tid / 6, t = tid % 6;
        int g = batch[n0 + nn];
        const float* kv = kvecs + (g * T_ + t) * 3;
        float ph = positions[(n0 + nn) * 3 + 0] * kv[0]
                 + positions[(n0 + nn) * 3 + 1] * kv[1]
                 + positions[(n0 + nn) * 3 + 2] * kv[2];
        float sv, cv;
        sincosf(ph, &sv, &cv);
        s_c[nn * 8 + t] = cv; s_s[nn * 8 + t] = sv;
    }
    __syncthreads();

#pragma unroll
    for (int p = 0; p < 48; p++) {
        int l = p * 256 + tid;
        int nn = l / 384, idx = l - nn * 384;
        int t = idx >> 6, d = idx & 63;
        int m2 = (d & 31) * 2;
        float c = s_c[nn * 8 + t], sv = s_s[nn * 8 + t];
        float qa = s_qkv[nn * 200 + m2],       qb = s_qkv[nn * 200 + m2 + 1];
        float ka = s_qkv[nn * 200 + 64 + m2],  kb = s_qkv[nn * 200 + 64 + m2 + 1];
        float qv, kvv;
        if (d < 32) { qv = qa * c  - qb * sv;  kvv = ka * c  - kb * sv; }
        else        { qv = qa * sv + qb * c;   kvv = ka * sv + kb * c;  }
        int n = n0 + nn;
        g_qr16[n * TD_ + idx] = __float2half_rn(qv * 0.125f);
        g_k16 [n * TD_ + idx] = __float2half_rn(kvv);
    }
#pragma unroll
    for (int p = 0; p < 8; p++) {
        int l = p * 256 + tid;
        int nn = l >> 6, m = l & 63;
        g_v16[(n0 + nn) * H_ + m] = __float2half_rn(s_qkv[nn * 200 + 128 + m]);
    }
}

// ---------------- K2: FUSED kv_graph + update, per (g,t) block ----------------
#define KU_KT   0        // phase1 kT: 64 x 144 = 9216 ; phase2: reused as TILE
#define KU_V    9216     // phase1 v : 64 x 144 = 9216 ; phase2: reused as Q
#define KU_SMEM 18432

__global__ void __launch_bounds__(256) k_kvgupd() {
    __shared__ __align__(16) char sm[KU_SMEM];
    uint32_t sb = smem_u32(sm);
    int bid = blockIdx.x;
    int g = bid / T_, t = bid % T_;
    int tid = threadIdx.x;
    int lane = tid & 31, w = tid >> 5;
    int wm = w & 3, wn = w >> 2;          // phase1: m16 of d, e32 half

    int s = g_seg[g], e = g_seg[g + 1];
    int nb0 = s & ~63;

    int rfr = (lane & 7) + ((lane >> 3) & 1) * 8;
    int cfr = (lane >> 4) * 16;

    float acc[4][4];
#pragma unroll
    for (int nt = 0; nt < 4; nt++)
#pragma unroll
        for (int q = 0; q < 4; q++) acc[nt][q] = 0.f;

    int pp = tid & 31, oo = tid >> 5;     // n-pair 0..31, d-oct 0..7

    // ===== Phase 1: kv_graph tile =====
    for (int nb = nb0; nb < e; nb += 64) {
        int n1 = nb + 2 * pp, n2 = n1 + 1;
        uint4 ra = make_uint4(0u,0u,0u,0u), rb = ra;
        if (n1 >= s && n1 < e) ra = *(const uint4*)(g_k16 + n1 * TD_ + t * 64 + oo * 8);
        if (n2 >= s && n2 < e) rb = *(const uint4*)(g_k16 + n2 * TD_ + t * 64 + oo * 8);
        const __half* ah = (const __half*)&ra;
        const __half* bh = (const __half*)&rb;
#pragma unroll
        for (int dd = 0; dd < 8; dd++) {
            __half2 h = __halves2half2(ah[dd], bh[dd]);
            *(__half2*)(sm + KU_KT + (oo * 8 + dd) * RSTRIDE + pp * 4) = h;
        }
#pragma unroll
        for (int p = 0; p < 2; p++) {
            int idx = p * 256 + tid;
            int r = idx >> 3, q8 = idx & 7;
            int n = nb + r;
            uint4 val = make_uint4(0u, 0u, 0u, 0u);
            if (n >= s && n < e) val = *(const uint4*)(g_v16 + n * H_ + q8 * 8);
            *(uint4*)(sm + KU_V + r * RSTRIDE + q8 * 16) = val;
        }
        __syncthreads();

#pragma unroll
        for (int ks = 0; ks < 4; ks++) {
            uint32_t aF[4], bF[8];
            LDSM_X4(aF, sb + KU_KT + (uint32_t)(wm * 16 + rfr) * RSTRIDE + cfr + ks * 32);
            LDSM_X4T(&bF[0], sb + KU_V + (uint32_t)(ks * 16 + rfr) * RSTRIDE + wn * 64 + cfr);
            LDSM_X4T(&bF[4], sb + KU_V + (uint32_t)(ks * 16 + rfr) * RSTRIDE + wn * 64 + 32 + cfr);
            mma16816h(acc[0], aF, &bF[0]);
            mma16816h(acc[1], aF, &bF[2]);
            mma16816h(acc[2], aF, &bF[4]);
            mma16816h(acc[3], aF, &bF[6]);
        }
        __syncthreads();
    }

    // ===== write tile to smem fp16 (reuse KU_KT region: [64 d rows][64 e]) =====
    {
        int d0 = wm * 16 + (lane >> 2);
        int cb = 2 * (lane & 3);
#pragma unroll
        for (int nt = 0; nt < 4; nt++) {
            int ec = wn * 32 + nt * 8 + cb;
            *(__half2*)(sm + KU_KT + d0 * RSTRIDE + ec * 2) =
                __floats2half2_rn(acc[nt][0], acc[nt][1]);
            *(__half2*)(sm + KU_KT + (d0 + 8) * RSTRIDE + ec * 2) =
                __floats2half2_rn(acc[nt][2], acc[nt][3]);
        }
    }
    __syncthreads();

    // ===== Phase 2: updf[n,e] += q[n, t*64: ] @ tile, per 64-node chunk =====
    int weg = wn;
    for (int nb = nb0; nb < e; nb += 64) {
#pragma unroll
        for (int p = 0; p < 2; p++) {
            int idx = p * 256 + tid;
            int nl = idx >> 3, q8 = idx & 7;
            int n = nb + nl;
            uint4 val = make_uint4(0u, 0u, 0u, 0u);
            if (n >= s && n < e) val = *(const uint4*)(g_qr16 + n * TD_ + t * 64 + q8 * 8);
            *(uint4*)(sm + KU_V + nl * RSTRIDE + q8 * 16) = val;
        }
        __syncthreads();

        float pacc[4][4];
#pragma unroll
        for (int nt = 0; nt < 4; nt++)
#pragma unroll
            for (int q = 0; q < 4; q++) pacc[nt][q] = 0.f;

        uint32_t aB = sb + KU_V  + (uint32_t)(wm * 16 + rfr) * RSTRIDE + cfr;
        uint32_t bB = sb + KU_KT + (uint32_t)rfr * RSTRIDE + weg * 64 + cfr;
#pragma unroll
        for (int ks = 0; ks < 4; ks++) {
            uint32_t aF[4], bF[8];
            LDSM_X4(aF, aB + ks * 32);
            LDSM_X4T(&bF[0], bB + ks * (16 * RSTRIDE));
            LDSM_X4T(&bF[4], bB + ks * (16 * RSTRIDE) + 32);
            mma16816h(pacc[0], aF, &bF[0]);
            mma16816h(pacc[1], aF, &bF[2]);
            mma16816h(pacc[2], aF, &bF[4]);
            mma16816h(pacc[3], aF, &bF[6]);
        }

        int r0 = wm * 16 + (lane >> 2);
        int cb = 2 * (lane & 3);
        int n1 = nb + r0, n2 = n1 + 8;
#pragma unroll
        for (int nt = 0; nt < 4; nt++) {
            int ec = weg * 32 + nt * 8 + cb;
            if (n1 >= s && n1 < e) {
                atomicAdd(&g_updf[n1 * H_ + ec],     pacc[nt][0]);
                atomicAdd(&g_updf[n1 * H_ + ec + 1], pacc[nt][1]);
            }
            if (n2 >= s && n2 < e) {
                atomicAdd(&g_updf[n2 * H_ + ec],     pacc[nt][2]);
                atomicAdd(&g_updf[n2 * H_ + ec + 1], pacc[nt][3]);
            }
        }
        __syncthreads();
    }
}

// ---------------- K3: tensor-product GEMM, fragment-direct B, sync-free -------
// 4m x 2n warp tiling; B fragments LDG'd straight from g_Bf; one sync total.
#define TP_U    0
#define TP_NF   18432
#define TP_SMEM 22528

__global__ void __launch_bounds__(256, 2) k_tpmma(const float* __restrict__ nfsr,
                                                  float* __restrict__ out) {
    extern __shared__ char smem[];
    uint32_t sb = smem_u32(smem);
    int tid = threadIdx.x;
    int wid = tid >> 5, lane = tid & 31;
    int n0 = blockIdx.x * 128;
    int i0 = blockIdx.y * 8;
    int wm = wid & 3, wn = wid >> 2;

    float* s_nf = (float*)(smem + TP_NF);     // [c][128], c<8

#pragma unroll
    for (int p = 0; p < 4; p++) {
        int l = p * 256 + tid;                 // 0..1023
        int nl = l >> 3, ii = l & 7;
        s_nf[ii * 128 + nl] = nfsr[(n0 + nl) * H_ + i0 + ii];
    }
    // build fp16 U tile from fp32 g_updf
#pragma unroll
    for (int p = 0; p < 4; p++) {
        int idx = p * 256 + tid;              // 0..1023
        int n = idx >> 3, q8 = idx & 7;
        const float4* src = (const float4*)(g_updf + (n0 + n) * H_ + q8 * 8);
        float4 u0 = src[0], u1 = src[1];
        __half2 h0 = __floats2half2_rn(u0.x, u0.y);
        __half2 h1 = __floats2half2_rn(u0.z, u0.w);
        __half2 h2 = __floats2half2_rn(u1.x, u1.y);
        __half2 h3 = __floats2half2_rn(u1.z, u1.w);
        uint4 val = make_uint4(*(uint32_t*)&h0, *(uint32_t*)&h1,
                               *(uint32_t*)&h2, *(uint32_t*)&h3);
        *(uint4*)(smem + TP_U + n * RSTRIDE + q8 * 16) = val;
    }
    __syncthreads();

    int rfr = (lane & 7) + ((lane >> 3) & 1) * 8;
    int cfr = (lane >> 4) * 16;

    // resident A fragments: 2 m16 tiles x 4 k-steps (fp16 upd)
    uint32_t aF[32];
#pragma unroll
    for (int mt = 0; mt < 2; mt++) {
        uint32_t aAddr = sb + TP_U + (uint32_t)(wm * 32 + mt * 16 + rfr) * RSTRIDE + cfr;
#pragma unroll
        for (int ks = 0; ks < 4; ks++) LDSM_X4(&aF[mt * 16 + ks * 4], aAddr + ks * 32);
    }

    float acc[2][4][4];
#pragma unroll
    for (int mt = 0; mt < 2; mt++)
#pragma unroll
        for (int nt = 0; nt < 4; nt++)
#pragma unroll
            for (int q = 0; q < 4; q++) acc[mt][nt][q] = 0.f;

    int rowl = wm * 32 + (lane >> 2);

    for (int c = 0; c < 8; c++) {
        int i = i0 + c;
        // load this chunk's B fragments: 8 x LDG.128, independent
        uint32_t bF[32];
#pragma unroll
        for (int ks = 0; ks < 4; ks++) {
            const uint4* bp = (const uint4*)(g_Bf +
                ((uint32_t)(((i * 2 + wn) * 4 + ks) * 32 + lane) << 3));
            uint4 x = __ldg(bp), y = __ldg(bp + 1);
            bF[ks * 8 + 0] = x.x; bF[ks * 8 + 1] = x.y;
            bF[ks * 8 + 2] = x.z; bF[ks * 8 + 3] = x.w;
            bF[ks * 8 + 4] = y.x; bF[ks * 8 + 5] = y.y;
            bF[ks * 8 + 6] = y.z; bF[ks * 8 + 7] = y.w;
        }
        __half2 f0[2], f1[2];
#pragma unroll
        for (int mt = 0; mt < 2; mt++) {
            f0[mt] = __float2half2_rn(s_nf[c * 128 + rowl + mt * 16]);
            f1[mt] = __float2half2_rn(s_nf[c * 128 + rowl + mt * 16 + 8]);
        }
#pragma unroll
        for (int ks = 0; ks < 4; ks++) {
#pragma unroll
            for (int mt = 0; mt < 2; mt++) {
                const uint32_t* a4 = &aF[mt * 16 + ks * 4];
                uint32_t sF[4];
                __half2 s0 = __hmul2(*(const __half2*)&a4[0], f0[mt]);
                __half2 s1 = __hmul2(*(const __half2*)&a4[1], f1[mt]);
                __half2 s2 = __hmul2(*(const __half2*)&a4[2], f0[mt]);
                __half2 s3 = __hmul2(*(const __half2*)&a4[3], f1[mt]);
                sF[0] = *(uint32_t*)&s0; sF[1] = *(uint32_t*)&s1;
                sF[2] = *(uint32_t*)&s2; sF[3] = *(uint32_t*)&s3;
#pragma unroll
                for (int nt = 0; nt < 4; nt++)
                    mma16816h(acc[mt][nt], sF, &bF[ks * 8 + nt * 2]);
            }
        }
    }

    int colb = 2 * (lane & 3);
#pragma unroll
    for (int mt = 0; mt < 2; mt++) {
        int row0 = n0 + wm * 32 + mt * 16 + (lane >> 2);
#pragma unroll
        for (int nt = 0; nt < 4; nt++) {
            int col = wn * 32 + nt * 8 + colb;
            atomicAdd(&out[row0 * H_ + col],           acc[mt][nt][0]);
            atomicAdd(&out[row0 * H_ + col + 1],       acc[mt][nt][1]);
            atomicAdd(&out[(row0 + 8) * H_ + col],     acc[mt][nt][2]);
            atomicAdd(&out[(row0 + 8) * H_ + col + 1], acc[mt][nt][3]);
        }
    }
}

// ---------------- launch ----------------
extern "C" void kernel_launch(void* const* d_in, const int* in_sizes, int n_in,
                              void* d_out, int out_size) {
    const float* node_feat    = (const float*)d_in[0];
    const float* node_feat_sr = (const float*)d_in[1];
    const float* positions    = (const float*)d_in[2];
    const float* kvecs        = (const float*)d_in[3];
    const int*   batch        = (const int*)  d_in[4];
    const float* W_readout    = (const float*)d_in[5];
    const float* W_qkv        = (const float*)d_in[6];
    const float* W_tp         = (const float*)d_in[7];
    float* out = (float*)d_out;

    static int attr_done = 0;
    if (!attr_done) {
        cudaFuncSetAttribute(k_qkv, cudaFuncAttributeMaxDynamicSharedMemorySize, QKV_SMEM);
        attr_done = 1;
    }

    k_prep   <<<145, 256>>>(W_qkv, W_readout, W_tp, batch, out);
    k_qkv    <<<N_ / 32, 256, QKV_SMEM>>>(node_feat, positions, kvecs, batch);
    k_kvgupd <<<G_ * T_, 256>>>();
    k_tpmma  <<<dim3(N_ / 128, 8), 256, TP_SMEM>>>(node_feat_sr, out);
}